// round 5
// baseline (speedup 1.0000x reference)
#include <cuda_runtime.h>
#include <cuda_fp16.h>
#include <cstdint>

#define NB  2
#define SEQ 1024
#define DIM 1024
#define NH  16
#define DK  64
#define FF  4096
#define NL  4
#define MROWS (NB*SEQ)   // 2048
#define QKVW 3072
#define LSC  256.0f      // lo-term pre-scale
#define ISC  (1.0f/256.0f)

// ---------------- PTX helpers (baseline sm_103 — NO arch-feature suffix) -----
__device__ __forceinline__ uint32_t smem_to_u32(const void* p) {
    uint32_t a;
    asm("{ .reg .u64 t; cvta.to.shared.u64 t, %1; cvt.u32.u64 %0, t; }" : "=r"(a) : "l"(p));
    return a;
}
__device__ __forceinline__ void cpasync16(uint32_t dst, const void* src) {
    asm volatile("cp.async.cg.shared.global [%0], [%1], 16;"
                 :: "r"(dst), "l"(__cvta_generic_to_global(src)) : "memory");
}
__device__ __forceinline__ void cpcommit() { asm volatile("cp.async.commit_group;" ::: "memory"); }
__device__ __forceinline__ void cpwait0()  { asm volatile("cp.async.wait_group 0;" ::: "memory"); }
__device__ __forceinline__ void cpwait1()  { asm volatile("cp.async.wait_group 1;" ::: "memory"); }

__device__ __forceinline__ void ldsm4(uint32_t& r0, uint32_t& r1, uint32_t& r2, uint32_t& r3,
                                      uint32_t a) {
    asm volatile("ldmatrix.sync.aligned.m8n8.x4.shared.b16 {%0,%1,%2,%3}, [%4];"
                 : "=r"(r0), "=r"(r1), "=r"(r2), "=r"(r3) : "r"(a));
}
__device__ __forceinline__ void ldsm4t(uint32_t& r0, uint32_t& r1, uint32_t& r2, uint32_t& r3,
                                       uint32_t a) {
    asm volatile("ldmatrix.sync.aligned.m8n8.x4.trans.shared.b16 {%0,%1,%2,%3}, [%4];"
                 : "=r"(r0), "=r"(r1), "=r"(r2), "=r"(r3) : "r"(a));
}
// f16 inputs, f32 accumulate (precision term)
__device__ __forceinline__ void mmaF(float* d, const uint32_t* a, const uint32_t* b) {
    asm volatile("mma.sync.aligned.m16n8k16.row.col.f32.f16.f16.f32 "
                 "{%0,%1,%2,%3}, {%4,%5,%6,%7}, {%8,%9}, {%0,%1,%2,%3};"
                 : "+f"(d[0]), "+f"(d[1]), "+f"(d[2]), "+f"(d[3])
                 : "r"(a[0]), "r"(a[1]), "r"(a[2]), "r"(a[3]), "r"(b[0]), "r"(b[1]));
}
// f16 inputs, f16 accumulate (lo terms — hopefully full-rate)
__device__ __forceinline__ void mmaH(uint32_t* d, const uint32_t* a, const uint32_t* b) {
    asm volatile("mma.sync.aligned.m16n8k16.row.col.f16.f16.f16.f16 "
                 "{%0,%1}, {%2,%3,%4,%5}, {%6,%7}, {%0,%1};"
                 : "+r"(d[0]), "+r"(d[1])
                 : "r"(a[0]), "r"(a[1]), "r"(a[2]), "r"(a[3]), "r"(b[0]), "r"(b[1]));
}
__device__ __forceinline__ uint32_t packh(float a, float b) {
    __half2 h = __floats2half2_rn(a, b);
    return *(uint32_t*)&h;
}
__device__ __forceinline__ float2 unpackh(uint32_t u) {
    return __half22float2(*(__half2*)&u);
}

// ---------------- scratch (static device memory) -----------------------------
__device__ float g_X  [MROWS*DIM];
__device__ float g_X1 [MROWS*DIM];
__device__ float g_Yb [MROWS*DIM];
__device__ __half g_Xhi [MROWS*DIM],  g_Xlo [MROWS*DIM];
__device__ __half g_X1hi[MROWS*DIM],  g_X1lo[MROWS*DIM];
__device__ __half g_Yhi [MROWS*DIM],  g_Ylo [MROWS*DIM];
__device__ __half g_QKVhi[MROWS*QKVW], g_QKVlo[MROWS*QKVW];
__device__ __half g_Ohi [MROWS*DIM],  g_Olo [MROWS*DIM];
__device__ __half g_Hhi [MROWS*FF],   g_Hlo [MROWS*FF];
__device__ __half g_Whi[64u*1024*1024];
__device__ __half g_Wlo[64u*1024*1024];
__device__ float  g_bQKV1[NL*QKVW], g_bQKV2[NL*QKVW];

#define LAYER_W  (16u*1024*1024)
#define OFF_Q1   (0u)
#define OFF_O1   (3u*1024*1024)
#define OFF_Q2   (4u*1024*1024)
#define OFF_O2   (7u*1024*1024)
#define OFF_W1   (8u*1024*1024)
#define OFF_W2   (12u*1024*1024)

// ---------------- activation split: fp32 -> (hi, lo*256) f16 -----------------
__global__ __launch_bounds__(256) void split_f32(const float* __restrict__ x,
        __half* __restrict__ h, __half* __restrict__ l, int n4)
{
    int i = blockIdx.x * 256 + threadIdx.x;
    if (i >= n4) return;
    float4 v = ((const float4*)x)[i];
    __half h0 = __float2half(v.x), h1 = __float2half(v.y);
    __half h2 = __float2half(v.z), h3 = __float2half(v.w);
    uint2 hp, lp;
    hp.x = packh(v.x, v.y); hp.y = packh(v.z, v.w);
    lp.x = packh((v.x - __half2float(h0))*LSC, (v.y - __half2float(h1))*LSC);
    lp.y = packh((v.z - __half2float(h2))*LSC, (v.w - __half2float(h3))*LSC);
    ((uint2*)h)[i] = hp;
    ((uint2*)l)[i] = lp;
}

// ------------- weight transpose+split: W[K,N](or head) -> Wt[N,K] hi/lo ------
__global__ __launch_bounds__(256) void wsplit_t(const float* __restrict__ W,
        __half* __restrict__ oh, __half* __restrict__ ol,
        int K, int N, size_t inLayerStride, size_t outOff, int headMode)
{
    __shared__ float t[32][33];
    int tx = threadIdx.x & 31, ty = threadIdx.x >> 5;
    int k0 = blockIdx.x * 32, n0 = blockIdx.y * 32;
    const float* Win = W + (size_t)blockIdx.z * inLayerStride;
    size_t ob = (size_t)blockIdx.z * LAYER_W + outOff;
#pragma unroll
    for (int i = 0; i < 4; i++) {
        int k = k0 + ty + 8*i, n = n0 + tx;
        size_t idx = headMode ? ((size_t)(n >> 6) * K * 64 + (size_t)k * 64 + (n & 63))
                              : ((size_t)k * N + n);
        t[ty + 8*i][tx] = Win[idx];
    }
    __syncthreads();
#pragma unroll
    for (int i = 0; i < 4; i++) {
        int n = n0 + ty + 8*i, k = k0 + tx;
        float v = t[tx][ty + 8*i];
        __half hi = __float2half(v);
        oh[ob + (size_t)n * K + k] = hi;
        ol[ob + (size_t)n * K + k] = __float2half((v - __half2float(hi)) * LSC);
    }
}

// ---------------- bias concat for fused QKV ----------------------------------
__global__ __launch_bounds__(256) void pack_bias(const float* __restrict__ bq,
        const float* __restrict__ bk, const float* __restrict__ bv,
        float* __restrict__ out)
{
    int l = blockIdx.y;
    int i = blockIdx.x * 256 + threadIdx.x;   // 0..1023
    out[l*QKVW + i]        = bq[l*1024 + i];
    out[l*QKVW + 1024 + i] = bk[l*1024 + i];
    out[l*QKVW + 2048 + i] = bv[l*1024 + i];
}

// ---------------- split-f16 HMMA GEMM ----------------------------------------
// C = A(2048xK) @ B^T + bias (+R) (+relu); optional split-f16 output (Chi/Clo)
#define RSB 144
#define STAGE_BYTES (4*128*RSB)
#define SA_HI 0
#define SA_LO 18432
#define SB_HI 36864
#define SB_LO 55296
#define GEMM_SMEM (2*STAGE_BYTES)

__global__ __launch_bounds__(256, 1) void gemm_tc(
        const __half* __restrict__ Ah, const __half* __restrict__ Al,
        const __half* __restrict__ Bh, const __half* __restrict__ Bl,
        const float* __restrict__ bias, const float* __restrict__ R,
        float* __restrict__ C,
        __half* __restrict__ Chi, __half* __restrict__ Clo,
        int N, int K, int relu)
{
    extern __shared__ char smem[];
    const uint32_t sb = smem_to_u32(smem);
    const int tid = threadIdx.x, lane = tid & 31, wid = tid >> 5;
    const int wm = wid & 1, wn = wid >> 1;
    const int m0 = blockIdx.y * 128, n0 = blockIdx.x * 128;

    float acc[4][4][4];
    uint32_t accL[4][4][2];
#pragma unroll
    for (int i = 0; i < 4; i++)
#pragma unroll
        for (int j = 0; j < 4; j++) {
#pragma unroll
            for (int q = 0; q < 4; q++) acc[i][j][q] = 0.f;
            accL[i][j][0] = 0u; accL[i][j][1] = 0u;
        }

    const int nch = K >> 6;
    auto issue_stage = [&](int ch, int stg) {
        const int k0 = ch << 6;
        const uint32_t base = sb + stg * STAGE_BYTES;
#pragma unroll
        for (int i = tid; i < 1024; i += 256) {
            int r = i >> 3, c = i & 7;
            uint32_t doff = r * RSB + c * 16;
            size_t aoff = (size_t)(m0 + r) * K + k0 + c * 8;
            size_t boff = (size_t)(n0 + r) * K + k0 + c * 8;
            cpasync16(base + SA_HI + doff, Ah + aoff);
            cpasync16(base + SA_LO + doff, Al + aoff);
            cpasync16(base + SB_HI + doff, Bh + boff);
            cpasync16(base + SB_LO + doff, Bl + boff);
        }
        cpcommit();
    };

    issue_stage(0, 0);

    const uint32_t aAddr = (uint32_t)((wm*64 + (lane & 15)) * RSB + (lane >> 4) * 16);
    const uint32_t bAddr = (uint32_t)((wn*32 + (lane & 7) + ((lane >> 4) & 1) * 8) * RSB
                                      + ((lane >> 3) & 1) * 16);

    for (int ch = 0; ch < nch; ch++) {
        cpwait0();
        __syncthreads();
        if (ch + 1 < nch) issue_stage(ch + 1, (ch + 1) & 1);
        const uint32_t stg = sb + (ch & 1) * STAGE_BYTES;
#pragma unroll
        for (int ks = 0; ks < 4; ks++) {
            uint32_t ah[4][4], al[4][4], bh[2][4], bl[2][4];
#pragma unroll
            for (int ma = 0; ma < 4; ma++) {
                uint32_t ad = stg + SA_HI + aAddr + ma * (16 * RSB) + ks * 32;
                ldsm4(ah[ma][0], ah[ma][1], ah[ma][2], ah[ma][3], ad);
                ldsm4(al[ma][0], al[ma][1], al[ma][2], al[ma][3], ad + (SA_LO - SA_HI));
            }
#pragma unroll
            for (int nb = 0; nb < 2; nb++) {
                uint32_t bd = stg + SB_HI + bAddr + nb * (16 * RSB) + ks * 32;
                ldsm4(bh[nb][0], bh[nb][1], bh[nb][2], bh[nb][3], bd);
                ldsm4(bl[nb][0], bl[nb][1], bl[nb][2], bl[nb][3], bd + (SB_LO - SB_HI));
            }
#pragma unroll
            for (int ma = 0; ma < 4; ma++)
#pragma unroll
                for (int na = 0; na < 4; na++) {
                    const uint32_t bhp[2] = { bh[na >> 1][(na & 1) * 2],
                                              bh[na >> 1][(na & 1) * 2 + 1] };
                    const uint32_t blp[2] = { bl[na >> 1][(na & 1) * 2],
                                              bl[na >> 1][(na & 1) * 2 + 1] };
                    mmaF(acc[ma][na], ah[ma], bhp);
                    mmaH(accL[ma][na], ah[ma], blp);
                    mmaH(accL[ma][na], al[ma], bhp);
                }
        }
        // merge f16 lo accumulators into f32 (per chunk; keeps f16 range small)
#pragma unroll
        for (int ma = 0; ma < 4; ma++)
#pragma unroll
            for (int na = 0; na < 4; na++) {
                float2 l0 = unpackh(accL[ma][na][0]);
                float2 l1 = unpackh(accL[ma][na][1]);
                acc[ma][na][0] += l0.x * ISC; acc[ma][na][1] += l0.y * ISC;
                acc[ma][na][2] += l1.x * ISC; acc[ma][na][3] += l1.y * ISC;
                accL[ma][na][0] = 0u; accL[ma][na][1] = 0u;
            }
    }

    const int g  = lane >> 2;
    const int qc = (lane & 3) * 2;
#pragma unroll
    for (int ma = 0; ma < 4; ma++) {
        const int row0 = m0 + wm*64 + ma*16 + g;
        const int row1 = row0 + 8;
#pragma unroll
        for (int na = 0; na < 4; na++) {
            const int col = n0 + wn*32 + na*8 + qc;
            const float b0 = bias[col], b1 = bias[col + 1];
            float v00 = acc[ma][na][0] + b0, v01 = acc[ma][na][1] + b1;
            float v10 = acc[ma][na][2] + b0, v11 = acc[ma][na][3] + b1;
            if (R) {
                float2 r0 = *(const float2*)&R[(size_t)row0 * N + col];
                float2 r1 = *(const float2*)&R[(size_t)row1 * N + col];
                v00 += r0.x; v01 += r0.y; v10 += r1.x; v11 += r1.y;
            }
            if (relu) {
                v00 = fmaxf(v00, 0.f); v01 = fmaxf(v01, 0.f);
                v10 = fmaxf(v10, 0.f); v11 = fmaxf(v11, 0.f);
            }
            if (Chi) {
                float h00 = __half2float(__float2half(v00));
                float h01 = __half2float(__float2half(v01));
                float h10 = __half2float(__float2half(v10));
                float h11 = __half2float(__float2half(v11));
                *(uint32_t*)&Chi[(size_t)row0 * N + col] = packh(v00, v01);
                *(uint32_t*)&Chi[(size_t)row1 * N + col] = packh(v10, v11);
                *(uint32_t*)&Clo[(size_t)row0 * N + col] = packh((v00-h00)*LSC, (v01-h01)*LSC);
                *(uint32_t*)&Clo[(size_t)row1 * N + col] = packh((v10-h10)*LSC, (v11-h11)*LSC);
            } else {
                *(float2*)&C[(size_t)row0 * N + col] = make_float2(v00, v01);
                *(float2*)&C[(size_t)row1 * N + col] = make_float2(v10, v11);
            }
        }
    }
}

// ---------------- HMMA flash attention (split-f16) ---------------------------
// Q/K/V read from fused QKV buffer [token][3072]; O written split (stride DIM).
#define ARS 144
#define AQ_HI 0
#define AQ_LO 18432
#define AKV0  36864
#define AKV_STAGE 36864
#define ATT_SMEM (AKV0 + 2*AKV_STAGE)   // 110592

__global__ __launch_bounds__(256, 2) void attn_tc(
        const __half* __restrict__ QKVh, const __half* __restrict__ QKVl,
        __half* __restrict__ Ohi, __half* __restrict__ Olo,
        const int* __restrict__ mask_ptr)
{
    extern __shared__ char smem[];
    const uint32_t sb = smem_to_u32(smem);
    const int tid = threadIdx.x, lane = tid & 31, w = tid >> 5;
    const int q0 = blockIdx.x * 128, h = blockIdx.y, b = blockIdx.z;
    const int lim = mask_ptr ? *mask_ptr : SEQ;
    const size_t tokbase = (size_t)b * SEQ;
    const int cq = h * DK, ck = 1024 + h * DK, cv = 2048 + h * DK;

    for (int i = tid; i < 1024; i += 256) {
        int r = i >> 3, c = i & 7;
        uint32_t qd = sb + r * ARS + c * 16;
        size_t gi = (tokbase + q0 + r) * QKVW + cq + c * 8;
        cpasync16(qd + AQ_HI, QKVh + gi);
        cpasync16(qd + AQ_LO, QKVl + gi);
    }
    auto ldkv = [&](int t, int stg) {
        uint32_t base = sb + AKV0 + stg * AKV_STAGE;
        for (int i = tid; i < 512; i += 256) {
            int r = i >> 3, c = i & 7;
            uint32_t off = r * ARS + c * 16;
            size_t row = (tokbase + t * 64 + r) * QKVW;
            cpasync16(base + off,         QKVh + row + ck + c * 8);
            cpasync16(base + 9216 + off,  QKVl + row + ck + c * 8);
            cpasync16(base + 18432 + off, QKVh + row + cv + c * 8);
            cpasync16(base + 27648 + off, QKVl + row + cv + c * 8);
        }
        cpcommit();
    };
    ldkv(0, 0);

    const int nt = (lim + 63) >> 6;
    const int g = lane >> 2, qc = (lane & 3) * 2;
    const int wq = w * 16;

    float m[2] = {-1e30f, -1e30f}, l[2] = {0.f, 0.f};
    float o[8][4];
#pragma unroll
    for (int i = 0; i < 8; i++)
#pragma unroll
        for (int j = 0; j < 4; j++) o[i][j] = 0.f;

    for (int t = 0; t < nt; t++) {
        __syncthreads();
        if (t + 1 < nt) { ldkv(t + 1, (t + 1) & 1); cpwait1(); }
        else           { cpwait0(); }
        __syncthreads();
        const uint32_t kb = sb + AKV0 + (t & 1) * AKV_STAGE;

        // ---- scores: hi term f32-acc, lo terms f16-acc ----
        float sc[8][4];
        uint32_t scL[8][2];
#pragma unroll
        for (int i = 0; i < 8; i++) {
#pragma unroll
            for (int j = 0; j < 4; j++) sc[i][j] = 0.f;
            scL[i][0] = 0u; scL[i][1] = 0u;
        }

#pragma unroll
        for (int ks = 0; ks < 4; ks++) {
            uint32_t qa = sb + (wq + (lane & 15)) * ARS + (lane >> 4) * 16 + ks * 32;
            uint32_t qh[4], ql[4];
            ldsm4(qh[0], qh[1], qh[2], qh[3], qa + AQ_HI);
            ldsm4(ql[0], ql[1], ql[2], ql[3], qa + AQ_LO);
#pragma unroll
            for (int p = 0; p < 4; p++) {
                uint32_t ka = kb + (p*16 + (lane & 7) + ((lane >> 4) & 1) * 8) * ARS
                              + ((lane >> 3) & 1) * 16 + ks * 32;
                uint32_t kh[4], kl[4];
                ldsm4(kh[0], kh[1], kh[2], kh[3], ka);
                ldsm4(kl[0], kl[1], kl[2], kl[3], ka + 9216);
                const uint32_t kh01[2] = {kh[0], kh[1]}, kh23[2] = {kh[2], kh[3]};
                const uint32_t kl01[2] = {kl[0], kl[1]}, kl23[2] = {kl[2], kl[3]};
                mmaF(sc[2*p],   qh, kh01);
                mmaH(scL[2*p],  qh, kl01);
                mmaH(scL[2*p],  ql, kh01);
                mmaF(sc[2*p+1], qh, kh23);
                mmaH(scL[2*p+1], qh, kl23);
                mmaH(scL[2*p+1], ql, kh23);
            }
        }
#pragma unroll
        for (int na = 0; na < 8; na++) {
            float2 l0 = unpackh(scL[na][0]);
            float2 l1 = unpackh(scL[na][1]);
            sc[na][0] += l0.x * ISC; sc[na][1] += l0.y * ISC;
            sc[na][2] += l1.x * ISC; sc[na][3] += l1.y * ISC;
        }

        // ---- scale + mask ----
        const int t0 = t * 64;
#pragma unroll
        for (int na = 0; na < 8; na++) {
            int c0 = t0 + na*8 + qc, c1 = c0 + 1;
#pragma unroll
            for (int j = 0; j < 2; j++) {
                float s0 = sc[na][2*j]   * 0.125f;
                float s1 = sc[na][2*j+1] * 0.125f;
                sc[na][2*j]   = (c0 < lim) ? s0 : -1e30f;
                sc[na][2*j+1] = (c1 < lim) ? s1 : -1e30f;
            }
        }

        // ---- online softmax ----
#pragma unroll
        for (int j = 0; j < 2; j++) {
            float mx = -1e30f;
#pragma unroll
            for (int na = 0; na < 8; na++)
                mx = fmaxf(mx, fmaxf(sc[na][2*j], sc[na][2*j+1]));
            mx = fmaxf(mx, __shfl_xor_sync(0xffffffffu, mx, 1));
            mx = fmaxf(mx, __shfl_xor_sync(0xffffffffu, mx, 2));
            float mnew = fmaxf(m[j], mx);
            float corr = __expf(m[j] - mnew);
            l[j] *= corr;
            m[j] = mnew;
#pragma unroll
            for (int nd = 0; nd < 8; nd++) { o[nd][2*j] *= corr; o[nd][2*j+1] *= corr; }
            float sum = 0.f;
#pragma unroll
            for (int na = 0; na < 8; na++) {
                float p0 = __expf(sc[na][2*j]   - mnew);
                float p1 = __expf(sc[na][2*j+1] - mnew);
                sc[na][2*j] = p0; sc[na][2*j+1] = p1;
                sum += p0 + p1;
            }
            sum += __shfl_xor_sync(0xffffffffu, sum, 1);
            sum += __shfl_xor_sync(0xffffffffu, sum, 2);
            l[j] += sum;
        }

        // ---- O += P V: hi f32-acc, lo f16-acc merged per tile ----
        uint32_t oL[8][2];
#pragma unroll
        for (int i = 0; i < 8; i++) { oL[i][0] = 0u; oL[i][1] = 0u; }

#pragma unroll
        for (int kp = 0; kp < 4; kp++) {
            float p00 = sc[2*kp][0],   p01 = sc[2*kp][1];
            float p02 = sc[2*kp][2],   p03 = sc[2*kp][3];
            float p10 = sc[2*kp+1][0], p11 = sc[2*kp+1][1];
            float p12 = sc[2*kp+1][2], p13 = sc[2*kp+1][3];
            float h00 = __half2float(__float2half(p00));
            float h01 = __half2float(__float2half(p01));
            float h02 = __half2float(__float2half(p02));
            float h03 = __half2float(__float2half(p03));
            float h10 = __half2float(__float2half(p10));
            float h11 = __half2float(__float2half(p11));
            float h12 = __half2float(__float2half(p12));
            float h13 = __half2float(__float2half(p13));
            uint32_t aph[4] = { packh(p00, p01), packh(p02, p03),
                                packh(p10, p11), packh(p12, p13) };
            uint32_t apl[4] = { packh((p00-h00)*LSC, (p01-h01)*LSC),
                                packh((p02-h02)*LSC, (p03-h03)*LSC),
                                packh((p10-h10)*LSC, (p11-h11)*LSC),
                                packh((p12-h12)*LSC, (p13-h13)*LSC) };
#pragma unroll
            for (int vp = 0; vp < 4; vp++) {
                uint32_t va = kb + 18432 + (kp*16 + (lane & 15)) * ARS
                              + (vp*2 + (lane >> 4)) * 16;
                uint32_t vh[4], vl[4];
                ldsm4t(vh[0], vh[1], vh[2], vh[3], va);
                ldsm4t(vl[0], vl[1], vl[2], vl[3], va + 9216);
                const uint32_t vh01[2] = {vh[0], vh[1]}, vh23[2] = {vh[2], vh[3]};
                const uint32_t vl01[2] = {vl[0], vl[1]}, vl23[2] = {vl[2], vl[3]};
                mmaF(o[2*vp],   aph, vh01);
                mmaH(oL[2*vp],  aph, vl01);
                mmaH(oL[2*vp],  apl, vh01);
                mmaF(o[2*vp+1], aph, vh23);
                mmaH(oL[2*vp+1], aph, vl23);
                mmaH(oL[2*vp+1], apl, vh23);
            }
        }
#pragma unroll
        for (int nd = 0; nd < 8; nd++) {
            float2 l0 = unpackh(oL[nd][0]);
            float2 l1 = unpackh(oL[nd][1]);
            o[nd][0] += l0.x * ISC; o[nd][1] += l0.y * ISC;
            o[nd][2] += l1.x * ISC; o[nd][3] += l1.y * ISC;
        }
    }

    // ---- epilogue ----
#pragma unroll
    for (int j = 0; j < 2; j++) {
        float inv = 1.f / l[j];
        int row = q0 + wq + g + j*8;
        size_t gb = (tokbase + row) * DIM + h * DK;
#pragma unroll
        for (int nd = 0; nd < 8; nd++) {
            float v0 = o[nd][2*j] * inv, v1 = o[nd][2*j+1] * inv;
            float h0 = __half2float(__float2half(v0));
            float h1 = __half2float(__float2half(v1));
            *(uint32_t*)&Ohi[gb + nd*8 + qc] = packh(v0, v1);
            *(uint32_t*)&Olo[gb + nd*8 + qc] = packh((v0-h0)*LSC, (v1-h1)*LSC);
        }
    }
}

// ---------------- BatchNorm1d + fused split output ---------------------------
__global__ __launch_bounds__(256)
void bn_kernel(float* __restrict__ X, const float* __restrict__ g,
               const float* __restrict__ be,
               __half* __restrict__ Xh, __half* __restrict__ Xl)
{
    const int s = blockIdx.x;
    const int tid = threadIdx.x;
    float v[8];
    float sum = 0.f, sq = 0.f;
#pragma unroll
    for (int r = 0; r < 8; r++) {
        int idx = r*256 + tid;
        int b = idx >> 10, d = idx & 1023;
        float x = X[(size_t)(b*SEQ + s)*DIM + d];
        v[r] = x; sum += x; sq += x*x;
    }
#pragma unroll
    for (int off = 16; off; off >>= 1) {
        sum += __shfl_xor_sync(0xffffffffu, sum, off);
        sq  += __shfl_xor_sync(0xffffffffu, sq,  off);
    }
    __shared__ float ssum[8], ssq[8];
    if ((tid & 31) == 0) { ssum[tid>>5] = sum; ssq[tid>>5] = sq; }
    __syncthreads();
    sum = 0.f; sq = 0.f;
#pragma unroll
    for (int w = 0; w < 8; w++) { sum += ssum[w]; sq += ssq[w]; }
    const float mean = sum * (1.f/2048.f);
    const float var  = sq  * (1.f/2048.f) - mean*mean;
    const float inv  = rsqrtf(var + 1e-5f);
    const float sc   = g[s] * inv;
    const float sh   = be[s] - mean * sc;
#pragma unroll
    for (int r = 0; r < 8; r++) {
        int idx = r*256 + tid;
        int b = idx >> 10, d = idx & 1023;
        size_t gi = (size_t)(b*SEQ + s)*DIM + d;
        float y = v[r]*sc + sh;
        X[gi] = y;
        __half hi = __float2half(y);
        Xh[gi] = hi;
        Xl[gi] = __float2half((y - __half2float(hi)) * LSC);
    }
}

// ---------------- host orchestration ----------------------------------------
extern "C" void kernel_launch(void* const* d_in, const int* in_sizes, int n_in,
                              void* d_out, int out_size)
{
    const float* x   = (const float*)d_in[0];
    const float* Wq1 = (const float*)d_in[1];
    const float* bq1 = (const float*)d_in[2];
    const float* Wk1 = (const float*)d_in[3];
    const float* bk1 = (const float*)d_in[4];
    const float* Wv1 = (const float*)d_in[5];
    const float* bv1 = (const float*)d_in[6];
    const float* Wo1 = (const float*)d_in[7];
    const float* bo1 = (const float*)d_in[8];
    const float* Wq2 = (const float*)d_in[9];
    const float* bq2 = (const float*)d_in[10];
    const float* Wk2 = (const float*)d_in[11];
    const float* bk2 = (const float*)d_in[12];
    const float* Wv2 = (const float*)d_in[13];
    const float* bv2 = (const float*)d_in[14];
    const float* Wo2 = (const float*)d_in[15];
    const float* bo2 = (const float*)d_in[16];
    const float* g1  = (const float*)d_in[17];
    const float* be1 = (const float*)d_in[18];
    const float* g2  = (const float*)d_in[19];
    const float* be2 = (const float*)d_in[20];
    const float* g3  = (const float*)d_in[21];
    const float* be3 = (const float*)d_in[22];
    const float* W1  = (const float*)d_in[23];
    const float* bf1 = (const float*)d_in[24];
    const float* W2  = (const float*)d_in[25];
    const float* bf2 = (const float*)d_in[26];
    const int*   msk = (const int*)d_in[27];

    float *X, *X1, *Y, *bQ1, *bQ2;
    __half *Whi, *Wlo;
    __half *Xhi, *Xlo, *X1hi, *X1lo, *Yhi, *Ylo;
    __half *QKVhi, *QKVlo, *Ohi, *Olo, *Hhi, *Hlo;
    cudaGetSymbolAddress((void**)&X,     g_X);
    cudaGetSymbolAddress((void**)&X1,    g_X1);
    cudaGetSymbolAddress((void**)&Y,     g_Yb);
    cudaGetSymbolAddress((void**)&Whi,   g_Whi);
    cudaGetSymbolAddress((void**)&Wlo,   g_Wlo);
    cudaGetSymbolAddress((void**)&Xhi,   g_Xhi);   cudaGetSymbolAddress((void**)&Xlo,   g_Xlo);
    cudaGetSymbolAddress((void**)&X1hi,  g_X1hi);  cudaGetSymbolAddress((void**)&X1lo,  g_X1lo);
    cudaGetSymbolAddress((void**)&Yhi,   g_Yhi);   cudaGetSymbolAddress((void**)&Ylo,   g_Ylo);
    cudaGetSymbolAddress((void**)&QKVhi, g_QKVhi); cudaGetSymbolAddress((void**)&QKVlo, g_QKVlo);
    cudaGetSymbolAddress((void**)&Ohi,   g_Ohi);   cudaGetSymbolAddress((void**)&Olo,   g_Olo);
    cudaGetSymbolAddress((void**)&Hhi,   g_Hhi);   cudaGetSymbolAddress((void**)&Hlo,   g_Hlo);
    cudaGetSymbolAddress((void**)&bQ1,   g_bQKV1); cudaGetSymbolAddress((void**)&bQ2,   g_bQKV2);

    cudaFuncSetAttribute(gemm_tc, cudaFuncAttributeMaxDynamicSharedMemorySize, GEMM_SMEM);
    cudaFuncSetAttribute(attn_tc, cudaFuncAttributeMaxDynamicSharedMemorySize, ATT_SMEM);

    const size_t bytesD = (size_t)MROWS * DIM * sizeof(float);
    cudaMemcpyAsync(X, x, bytesD, cudaMemcpyDeviceToDevice);

    // ---- weight transpose + split, bias concat ----
    {
        dim3 b(256);
        dim3 gQ(32, 32, NL);
        size_t sQKV = (size_t)NH * DIM * DK;
        wsplit_t<<<gQ, b>>>(Wq1, Whi, Wlo, 1024, 1024, sQKV, OFF_Q1 + 0u,        1);
        wsplit_t<<<gQ, b>>>(Wk1, Whi, Wlo, 1024, 1024, sQKV, OFF_Q1 + (1u<<20),  1);
        wsplit_t<<<gQ, b>>>(Wv1, Whi, Wlo, 1024, 1024, sQKV, OFF_Q1 + (2u<<20),  1);
        wsplit_t<<<gQ, b>>>(Wo1, Whi, Wlo, 1024, 1024, (size_t)DIM*DIM, OFF_O1,  0);
        wsplit_t<<<gQ, b>>>(Wq2, Whi, Wlo, 1024, 1024, sQKV, OFF_Q2 + 0u,        1);
        wsplit_t<<<gQ, b>>>(Wk2, Whi, Wlo, 1024, 1024, sQKV, OFF_Q2 + (1u<<20),  1);
        wsplit_t<<<gQ, b>>>(Wv2, Whi, Wlo, 1024, 1024, sQKV, OFF_Q2 + (2u<<20),  1);
        wsplit_t<<<gQ, b>>>(Wo2, Whi, Wlo, 1024, 1024, (size_t)DIM*DIM, OFF_O2,  0);
        wsplit_t<<<dim3(32, 128, NL), b>>>(W1, Whi, Wlo, 1024, 4096, (size_t)DIM*FF, OFF_W1, 0);
        wsplit_t<<<dim3(128, 32, NL), b>>>(W2, Whi, Wlo, 4096, 1024, (size_t)FF*DIM, OFF_W2, 0);
        pack_bias<<<dim3(4, NL), b>>>(bq1, bk1, bv1, bQ1);
        pack_bias<<<dim3(4, NL), b>>>(bq2, bk2, bv2, bQ2);
    }

    const int n4D = MROWS * DIM / 4;
    split_f32<<<n4D/256, 256>>>(X, Xhi, Xlo, n4D);

    dim3 gQKV(QKVW/128, MROWS/128);    // (24,16)
    dim3 gGD(DIM/128, MROWS/128);      // (8,16)
    dim3 gGF(FF/128,  MROWS/128);      // (32,16)
    dim3 gA(SEQ/128, NH, NB);          // (8,16,2)

    for (int l = 0; l < NL; l++) {
        const __half* WH = Whi + (size_t)l * LAYER_W;
        const __half* WL = Wlo + (size_t)l * LAYER_W;
        const size_t dO  = (size_t)l * DIM;
        const size_t f1O = (size_t)l * FF;

        // ---- masked self-attention (fused QKV GEMM) ----
        gemm_tc<<<gQKV, 256, GEMM_SMEM>>>(Xhi, Xlo, WH+OFF_Q1, WL+OFF_Q1, bQ1 + l*QKVW, nullptr, nullptr, QKVhi, QKVlo, QKVW, DIM, 0);
        attn_tc<<<gA, 256, ATT_SMEM>>>(QKVhi, QKVlo, Ohi, Olo, msk);
        gemm_tc<<<gGD, 256, GEMM_SMEM>>>(Ohi, Olo, WH+OFF_O1, WL+OFF_O1, bo1+dO, X, X1, nullptr, nullptr, DIM, DIM, 0);
        bn_kernel<<<SEQ, 256>>>(X1, g1+dO, be1+dO, X1hi, X1lo);

        // ---- second (unmasked) attention; residual from block input X ----
        gemm_tc<<<gQKV, 256, GEMM_SMEM>>>(X1hi, X1lo, WH+OFF_Q2, WL+OFF_Q2, bQ2 + l*QKVW, nullptr, nullptr, QKVhi, QKVlo, QKVW, DIM, 0);
        attn_tc<<<gA, 256, ATT_SMEM>>>(QKVhi, QKVlo, Ohi, Olo, nullptr);
        gemm_tc<<<gGD, 256, GEMM_SMEM>>>(Ohi, Olo, WH+OFF_O2, WL+OFF_O2, bo2+dO, X, Y, nullptr, nullptr, DIM, DIM, 0);
        bn_kernel<<<SEQ, 256>>>(Y, g2+dO, be2+dO, Yhi, Ylo);

        // ---- FFN; residual from X1 ----
        gemm_tc<<<gGF, 256, GEMM_SMEM>>>(Yhi, Ylo, WH+OFF_W1, WL+OFF_W1, bf1+f1O, nullptr, nullptr, Hhi, Hlo, FF, DIM, 1);
        gemm_tc<<<gGD, 256, GEMM_SMEM>>>(Hhi, Hlo, WH+OFF_W2, WL+OFF_W2, bf2+dO, X1, X, nullptr, nullptr, DIM, FF, 0);
        bn_kernel<<<SEQ, 256>>>(X, g3+dO, be3+dO, Xhi, Xlo);
    }

    cudaMemcpyAsync(d_out, X, bytesD, cudaMemcpyDeviceToDevice);
}